// round 5
// baseline (speedup 1.0000x reference)
#include <cuda_runtime.h>

// Fixed shapes for Latency_78632261255775:
//   x: [8, 3, 224, 224] fp32, T = 100
//   out: [8, 100, 3, 224, 224] fp32
#define N_ELEM   1204224        // 8*3*224*224
#define N4       301056         // N_ELEM/4
#define CHW4     37632          // CHW/4 (uchar4 / float4 units per batch-image)
#define BATCH    8
#define T_STEPS  100
#define T_PER    10
#define NBLOCKS  1176           // == N4/256; co-resident (8/SM x 148 SM = 1184)
#define NITEMS   11760          // 147 * 10 * 8 fill work items
#define J_ITERS  10             // NITEMS / NBLOCKS

__device__ unsigned int g_min_bits;     // zero-init; maintained as 0xFFFFFFFF.. by reset below? see note
__device__ unsigned int g_max_bits;
__device__ unsigned int g_bar1 = 0;
__device__ unsigned int g_bar2 = 0;
__device__ unsigned int g_exit = 0;
__device__ unsigned int g_min_init = 0; // flag: first-ever run initializes min cell
__device__ unsigned char g_spikes[N_ELEM];

// Order-preserving float <-> uint mapping (monotone for all finite floats).
__device__ __forceinline__ unsigned int f2u(float f) {
    unsigned int u = __float_as_uint(f);
    return (u & 0x80000000u) ? ~u : (u | 0x80000000u);
}
__device__ __forceinline__ float u2f(unsigned int u) {
    u = (u & 0x80000000u) ? (u & 0x7fffffffu) : ~u;
    return __uint_as_float(u);
}

__device__ __forceinline__ void spin_until(volatile unsigned int* ctr, unsigned int target) {
    while (*ctr < target) { __nanosleep(64); }
}

__global__ void __launch_bounds__(256, 8) fused_kernel(const float* __restrict__ x,
                                                       float* __restrict__ out) {
    __shared__ unsigned int s_min[8], s_max[8];
    int tid = threadIdx.x;
    int bid = blockIdx.x;
    int gi = bid * 256 + tid;              // 0 .. N4-1, exactly one float4 each

    // ---------- Phase 1: global min/max ----------
    float4 v = ((const float4*)x)[gi];
    unsigned int a = f2u(v.x), b_ = f2u(v.y), c = f2u(v.z), d = f2u(v.w);
    unsigned int lmin = min(min(a, b_), min(c, d));
    unsigned int lmax = max(max(a, b_), max(c, d));
    #pragma unroll
    for (int off = 16; off > 0; off >>= 1) {
        lmin = min(lmin, __shfl_down_sync(0xFFFFFFFFu, lmin, off));
        lmax = max(lmax, __shfl_down_sync(0xFFFFFFFFu, lmax, off));
    }
    int wid = tid >> 5, lid = tid & 31;
    if (lid == 0) { s_min[wid] = lmin; s_max[wid] = lmax; }
    __syncthreads();
    if (tid < 32) {
        lmin = (lid < 8) ? s_min[lid] : 0xFFFFFFFFu;
        lmax = (lid < 8) ? s_max[lid] : 0u;
        #pragma unroll
        for (int off = 4; off > 0; off >>= 1) {
            lmin = min(lmin, __shfl_down_sync(0xFFFFFFFFu, lmin, off));
            lmax = max(lmax, __shfl_down_sync(0xFFFFFFFFu, lmax, off));
        }
        if (lid == 0) {
            // g_min cell semantics: stores are in the monotone-uint domain.
            // Cells are reset to {0xFFFFFFFF, 0} by the previous run's last
            // exiter; very first run sees zero-init handled via atomic identity:
            // for min we use atomicMin against 0xFFFFFFFF-reset cell; the
            // first-ever launch has g_min_bits==0 which would be wrong, so the
            // reset-to-identity is done by checking g_min_init once.
            if (atomicExch(&g_min_init, 1u) == 0u) {
                // first arrival of first-ever run: publish identity first.
                atomicExch(&g_min_bits, 0xFFFFFFFFu);
            }
            // spin until identity is visible on the very first run
            while (((volatile unsigned int*)&g_min_bits)[0] == 0u &&
                   ((volatile unsigned int*)&g_min_init)[0] != 2u) {
                if (((volatile unsigned int*)&g_min_bits)[0] != 0u) break;
                __nanosleep(32);
                break; // single check is enough after exch ordering; avoid livelock
            }
            atomicMin(&g_min_bits, lmin);
            atomicMax(&g_max_bits, lmax);
            __threadfence();
            atomicAdd(&g_bar1, 1u);
        }
    }

    // ---------- Barrier 1 ----------
    if (tid == 0) {
        spin_until(&g_bar1, NBLOCKS);
        __threadfence();
    }
    __syncthreads();

    // ---------- Phase 2: spike indices (exact reference FP sequence) ----------
    float mn = u2f(((volatile unsigned int*)&g_min_bits)[0]);
    float mx = u2f(((volatile unsigned int*)&g_max_bits)[0]);
    float denom = __fadd_rn(__fsub_rn(mx, mn), 1e-8f);
    uchar4 st;
    {
        float xn = __fdiv_rn(__fsub_rn(v.x, mn), denom);
        st.x = (unsigned char)max(0, min(99, (int)__fmul_rn(__fsub_rn(1.0f, xn), 99.0f)));
    }
    {
        float xn = __fdiv_rn(__fsub_rn(v.y, mn), denom);
        st.y = (unsigned char)max(0, min(99, (int)__fmul_rn(__fsub_rn(1.0f, xn), 99.0f)));
    }
    {
        float xn = __fdiv_rn(__fsub_rn(v.z, mn), denom);
        st.z = (unsigned char)max(0, min(99, (int)__fmul_rn(__fsub_rn(1.0f, xn), 99.0f)));
    }
    {
        float xn = __fdiv_rn(__fsub_rn(v.w, mn), denom);
        st.w = (unsigned char)max(0, min(99, (int)__fmul_rn(__fsub_rn(1.0f, xn), 99.0f)));
    }
    ((uchar4*)g_spikes)[gi] = st;
    __threadfence();           // make our spike stores visible before arriving
    __syncthreads();
    if (tid == 0) atomicAdd(&g_bar2, 1u);

    // ---------- Barrier 2 ----------
    if (tid == 0) {
        spin_until(&g_bar2, NBLOCKS);
        __threadfence();
    }
    __syncthreads();

    // ---------- Phase 3: one-hot fill (R2-measured-best decomposition) ----------
    #pragma unroll 1
    for (int j = 0; j < J_ITERS; j++) {
        int item = bid + NBLOCKS * j;           // 0 .. NITEMS-1
        int b = item / 1470;                    // 1470 = 147 * 10
        int rem = item - b * 1470;
        int tgrp = rem / 147;
        int chw4_blk = rem - tgrp * 147;
        int chw4 = chw4_blk * 256 + tid;
        uchar4 sp = ((const uchar4*)g_spikes)[b * CHW4 + chw4];
        int sx = sp.x, sy = sp.y, sz = sp.z, sw = sp.w;
        int t0 = tgrp * T_PER;
        float4* base = (float4*)out + (size_t)(b * T_STEPS + t0) * CHW4 + chw4;
        #pragma unroll
        for (int k = 0; k < T_PER; k++) {
            int t = t0 + k;
            float4 o;
            o.x = (sx == t) ? 1.0f : 0.0f;
            o.y = (sy == t) ? 1.0f : 0.0f;
            o.z = (sz == t) ? 1.0f : 0.0f;
            o.w = (sw == t) ? 1.0f : 0.0f;
            __stcs(base + (size_t)k * CHW4, o);
        }
    }

    // ---------- Cleanup: last exiter resets barrier/minmax state ----------
    if (tid == 0) {
        unsigned int prev = atomicAdd(&g_exit, 1u);
        if (prev == NBLOCKS - 1) {
            g_bar1 = 0;
            g_bar2 = 0;
            g_exit = 0;
            g_min_bits = 0xFFFFFFFFu;   // identity for next run's atomicMin
            g_max_bits = 0u;            // identity for next run's atomicMax
            g_min_init = 2u;            // identity already in place from now on
            __threadfence();
        }
    }
}

extern "C" void kernel_launch(void* const* d_in, const int* in_sizes, int n_in,
                              void* d_out, int out_size) {
    const float* x = (const float*)d_in[0];
    float* out = (float*)d_out;
    fused_kernel<<<NBLOCKS, 256>>>(x, out);
}

// round 6
// speedup vs baseline: 1.0593x; 1.0593x over previous
#include <cuda_runtime.h>

// Fixed shapes for Latency_78632261255775:
//   x: [8, 3, 224, 224] fp32, T = 100
//   out: [8, 100, 3, 224, 224] fp32
#define N_ELEM   1204224        // 8*3*224*224
#define N4       301056         // N_ELEM/4
#define CHW4     37632          // CHW/4 (float4/uchar4 units per image)
#define BATCH    8
#define T_STEPS  100
#define T_PRE    10             // t-slices pre-zeroed in kernel 1
#define T_PER    10             // t-slices per fill thread
#define MM_BLOCKS 1176          // minmax blocks (= N4/256)
#define Z_FLOAT4  3010560       // 8 * T_PRE * CHW4 float4 zeros
#define Z_BLOCKS  11760         // Z_FLOAT4 / 256
#define PERB4     376320        // T_PRE * CHW4 (float4 per batch in zero slab)

__device__ unsigned int g_min_bits;
__device__ unsigned int g_max_bits;
__device__ unsigned int g_part_min[MM_BLOCKS];
__device__ unsigned int g_part_max[MM_BLOCKS];
__device__ unsigned int g_count = 0;   // reset by last minmax block (graph-replay safe)
__device__ unsigned char g_spikes[N_ELEM];

// Order-preserving float <-> uint mapping (monotone for all finite floats).
__device__ __forceinline__ unsigned int f2u(float f) {
    unsigned int u = __float_as_uint(f);
    return (u & 0x80000000u) ? ~u : (u | 0x80000000u);
}
__device__ __forceinline__ float u2f(unsigned int u) {
    u = (u & 0x80000000u) ? (u & 0x7fffffffu) : ~u;
    return __uint_as_float(u);
}

__device__ __forceinline__ void block_reduce_minmax(unsigned int& lmin, unsigned int& lmax,
                                                    unsigned int* s_min, unsigned int* s_max) {
    #pragma unroll
    for (int off = 16; off > 0; off >>= 1) {
        lmin = min(lmin, __shfl_down_sync(0xFFFFFFFFu, lmin, off));
        lmax = max(lmax, __shfl_down_sync(0xFFFFFFFFu, lmax, off));
    }
    int wid = threadIdx.x >> 5;
    int lid = threadIdx.x & 31;
    if (lid == 0) { s_min[wid] = lmin; s_max[wid] = lmax; }
    __syncthreads();
    if (threadIdx.x < 32) {
        int nw = blockDim.x >> 5;
        lmin = (lid < nw) ? s_min[lid] : 0xFFFFFFFFu;
        lmax = (lid < nw) ? s_max[lid] : 0u;
        #pragma unroll
        for (int off = 4; off > 0; off >>= 1) {
            lmin = min(lmin, __shfl_down_sync(0xFFFFFFFFu, lmin, off));
            lmax = max(lmax, __shfl_down_sync(0xFFFFFFFFu, lmax, off));
        }
    }
}

// Kernel 1: blocks [0, MM_BLOCKS) compute global min/max (R4 structure);
// blocks [MM_BLOCKS, MM_BLOCKS+Z_BLOCKS) zero the t<T_PRE output slab.
// The zero writes are independent of min/max and hide under the minmax
// latency/ramp floor (~7.7us measured, shape-independent).
__global__ void __launch_bounds__(256, 8) minmax_zero_kernel(const float* __restrict__ x,
                                                             float* __restrict__ out) {
    if (blockIdx.x >= MM_BLOCKS) {
        // ---- zero-fill part: out[b, t<T_PRE, :] = 0 ----
        int zi = (blockIdx.x - MM_BLOCKS) * 256 + threadIdx.x;   // 0 .. Z_FLOAT4-1
        int b = zi / PERB4;
        int r = zi - b * PERB4;
        float4 z = make_float4(0.f, 0.f, 0.f, 0.f);
        __stcs((float4*)out + (size_t)b * T_STEPS * CHW4 + r, z);
        return;
    }
    // ---- minmax part ----
    __shared__ unsigned int s_min[8], s_max[8];
    __shared__ bool s_last;
    unsigned int lmin = 0xFFFFFFFFu, lmax = 0u;
    int i = blockIdx.x * 256 + threadIdx.x;    // one float4 per thread, i < N4
    float4 v = ((const float4*)x)[i];
    unsigned int a = f2u(v.x), b_ = f2u(v.y), c = f2u(v.z), d = f2u(v.w);
    lmin = min(min(a, b_), min(c, d));
    lmax = max(max(a, b_), max(c, d));
    block_reduce_minmax(lmin, lmax, s_min, s_max);
    if (threadIdx.x == 0) {
        g_part_min[blockIdx.x] = lmin;
        g_part_max[blockIdx.x] = lmax;
        __threadfence();
        unsigned int prev = atomicAdd(&g_count, 1u);
        s_last = (prev == MM_BLOCKS - 1);
    }
    __syncthreads();
    if (s_last) {
        unsigned int fmin = 0xFFFFFFFFu, fmax = 0u;
        for (int i2 = threadIdx.x; i2 < MM_BLOCKS; i2 += 256) {
            fmin = min(fmin, g_part_min[i2]);
            fmax = max(fmax, g_part_max[i2]);
        }
        __syncthreads();   // s_min/s_max reuse
        block_reduce_minmax(fmin, fmax, s_min, s_max);
        if (threadIdx.x == 0) {
            g_min_bits = fmin;
            g_max_bits = fmax;
            g_count = 0;               // reset for next graph replay
        }
    }
}

// Kernel 2: per-element spike index as uint8.
// FP sequence must match the reference exactly (IEEE ops, no fma/reciprocal):
//   xn = (x - min) / ((max - min) + 1e-8)
//   st = clip(trunc((1 - xn) * 99), 0, 99)
__global__ void __launch_bounds__(256, 8) spike_kernel(const float* __restrict__ x) {
    int i = blockIdx.x * 256 + threadIdx.x;   // 0 .. N4-1
    float mn = u2f(g_min_bits);
    float mx = u2f(g_max_bits);
    float denom = __fadd_rn(__fsub_rn(mx, mn), 1e-8f);
    float4 v = ((const float4*)x)[i];
    uchar4 st;
    {
        float xn = __fdiv_rn(__fsub_rn(v.x, mn), denom);
        st.x = (unsigned char)max(0, min(99, (int)__fmul_rn(__fsub_rn(1.0f, xn), 99.0f)));
    }
    {
        float xn = __fdiv_rn(__fsub_rn(v.y, mn), denom);
        st.y = (unsigned char)max(0, min(99, (int)__fmul_rn(__fsub_rn(1.0f, xn), 99.0f)));
    }
    {
        float xn = __fdiv_rn(__fsub_rn(v.z, mn), denom);
        st.z = (unsigned char)max(0, min(99, (int)__fmul_rn(__fsub_rn(1.0f, xn), 99.0f)));
    }
    {
        float xn = __fdiv_rn(__fsub_rn(v.w, mn), denom);
        st.w = (unsigned char)max(0, min(99, (int)__fmul_rn(__fsub_rn(1.0f, xn), 99.0f)));
    }
    ((uchar4*)g_spikes)[i] = st;
}

// Kernel 3: grid (147, 10, 8).
//   y in [0,9): dense one-hot fill for t in [T_PRE, 100) — R2-measured-best
//               shape: 1 L2-hit spike load, T_PER coalesced streaming stores.
//   y == 9:     scatter pass — write 1.0f at the ~10% of elements whose
//               spike time lands in the pre-zeroed slab t < T_PRE.
__global__ void __launch_bounds__(256, 8) fill_kernel(float* __restrict__ out) {
    int chw4 = blockIdx.x * 256 + threadIdx.x;  // 0 .. CHW4-1
    int b = blockIdx.z;
    uchar4 st = ((const uchar4*)g_spikes)[b * CHW4 + chw4];
    int sx = st.x, sy = st.y, sz = st.z, sw = st.w;
    if (blockIdx.y < 9) {
        int t0 = T_PRE + blockIdx.y * T_PER;
        float4* base = (float4*)out + (size_t)(b * T_STEPS + t0) * CHW4 + chw4;
        #pragma unroll
        for (int k = 0; k < T_PER; k++) {
            int t = t0 + k;
            float4 o;
            o.x = (sx == t) ? 1.0f : 0.0f;
            o.y = (sy == t) ? 1.0f : 0.0f;
            o.z = (sz == t) ? 1.0f : 0.0f;
            o.w = (sw == t) ? 1.0f : 0.0f;
            __stcs(base + (size_t)k * CHW4, o);
        }
    } else {
        // scatter ones into the pre-zeroed t < T_PRE slab
        size_t fbase = ((size_t)b * T_STEPS * CHW4 + chw4) * 4;   // float index of elem 0
        if (sx < T_PRE) out[fbase + (size_t)sx * CHW4 * 4 + 0] = 1.0f;
        if (sy < T_PRE) out[fbase + (size_t)sy * CHW4 * 4 + 1] = 1.0f;
        if (sz < T_PRE) out[fbase + (size_t)sz * CHW4 * 4 + 2] = 1.0f;
        if (sw < T_PRE) out[fbase + (size_t)sw * CHW4 * 4 + 3] = 1.0f;
    }
}

extern "C" void kernel_launch(void* const* d_in, const int* in_sizes, int n_in,
                              void* d_out, int out_size) {
    const float* x = (const float*)d_in[0];
    float* out = (float*)d_out;

    minmax_zero_kernel<<<MM_BLOCKS + Z_BLOCKS, 256>>>(x, out);
    spike_kernel<<<MM_BLOCKS, 256>>>(x);
    dim3 fgrid(CHW4 / 256, 10, BATCH);    // (147, 9 fill-groups + 1 scatter, 8)
    fill_kernel<<<fgrid, 256>>>(out);
}

// round 7
// speedup vs baseline: 1.2102x; 1.1424x over previous
#include <cuda_runtime.h>

// Fixed shapes for Latency_78632261255775:
//   x: [8, 3, 224, 224] fp32, T = 100
//   out: [8, 100, 3, 224, 224] fp32
#define N_ELEM   1204224        // 8*3*224*224
#define N4       301056         // N_ELEM/4
#define CHW4     37632          // CHW/4 (float4/uchar4 units per image)
#define BATCH    8
#define T_STEPS  100
#define T_PER    10             // time-steps per fill thread (measured best)
#define MS_BLOCKS 1176          // = N4/256; co-resident (8/SM x 148 SM = 1184)

// Statically initialized to reduction identities; after each run, the fill
// kernel (which never reads them and runs strictly after the consumer)
// resets them for the next graph replay.
__device__ unsigned int g_min_bits = 0xFFFFFFFFu;  // monotone-uint domain
__device__ unsigned int g_max_bits = 0u;
__device__ unsigned int g_bar = 0;
__device__ unsigned char g_spikes[N_ELEM];

// Order-preserving float <-> uint mapping (monotone for all finite floats).
__device__ __forceinline__ unsigned int f2u(float f) {
    unsigned int u = __float_as_uint(f);
    return (u & 0x80000000u) ? ~u : (u | 0x80000000u);
}
__device__ __forceinline__ float u2f(unsigned int u) {
    u = (u & 0x80000000u) ? (u & 0x7fffffffu) : ~u;
    return __uint_as_float(u);
}

// Fused min/max + spike kernel.
// Phase 1: one float4 per thread (kept in registers), block reduce,
//          RED.MIN/MAX straight to the global cells (no partials array,
//          no last-block reduce -> shortest possible dependency chain).
// Barrier: single grid-wide spin (all blocks co-resident by construction).
// Phase 2: read final min/max, compute 4 spike indices with the exact
//          reference FP sequence (IEEE ops, no fma/reciprocal), store uchar4.
//   xn = (x - min) / ((max - min) + 1e-8)
//   st = clip(trunc((1 - xn) * 99), 0, 99)
__global__ void __launch_bounds__(256, 8) minmax_spike_kernel(const float* __restrict__ x) {
    __shared__ unsigned int s_min[8], s_max[8];
    int tid = threadIdx.x;
    int gi = blockIdx.x * 256 + tid;          // 0 .. N4-1, exactly one float4
    float4 v = ((const float4*)x)[gi];

    // ---- Phase 1: reduce ----
    unsigned int a = f2u(v.x), b_ = f2u(v.y), c = f2u(v.z), d = f2u(v.w);
    unsigned int lmin = min(min(a, b_), min(c, d));
    unsigned int lmax = max(max(a, b_), max(c, d));
    #pragma unroll
    for (int off = 16; off > 0; off >>= 1) {
        lmin = min(lmin, __shfl_down_sync(0xFFFFFFFFu, lmin, off));
        lmax = max(lmax, __shfl_down_sync(0xFFFFFFFFu, lmax, off));
    }
    int wid = tid >> 5, lid = tid & 31;
    if (lid == 0) { s_min[wid] = lmin; s_max[wid] = lmax; }
    __syncthreads();
    if (tid < 32) {
        lmin = (lid < 8) ? s_min[lid] : 0xFFFFFFFFu;
        lmax = (lid < 8) ? s_max[lid] : 0u;
        #pragma unroll
        for (int off = 4; off > 0; off >>= 1) {
            lmin = min(lmin, __shfl_down_sync(0xFFFFFFFFu, lmin, off));
            lmax = max(lmax, __shfl_down_sync(0xFFFFFFFFu, lmax, off));
        }
        if (lid == 0) {
            atomicMin(&g_min_bits, lmin);     // RED.MIN (no return use)
            atomicMax(&g_max_bits, lmax);     // RED.MAX
            __threadfence();
            atomicAdd(&g_bar, 1u);            // arrive
        }
    }

    // ---- Grid barrier (single) ----
    if (tid == 0) {
        while (((volatile unsigned int*)&g_bar)[0] < MS_BLOCKS) { __nanosleep(64); }
        __threadfence();
    }
    __syncthreads();

    // ---- Phase 2: spike indices from registers ----
    float mn = u2f(((volatile unsigned int*)&g_min_bits)[0]);
    float mx = u2f(((volatile unsigned int*)&g_max_bits)[0]);
    float denom = __fadd_rn(__fsub_rn(mx, mn), 1e-8f);
    uchar4 st;
    {
        float xn = __fdiv_rn(__fsub_rn(v.x, mn), denom);
        st.x = (unsigned char)max(0, min(99, (int)__fmul_rn(__fsub_rn(1.0f, xn), 99.0f)));
    }
    {
        float xn = __fdiv_rn(__fsub_rn(v.y, mn), denom);
        st.y = (unsigned char)max(0, min(99, (int)__fmul_rn(__fsub_rn(1.0f, xn), 99.0f)));
    }
    {
        float xn = __fdiv_rn(__fsub_rn(v.z, mn), denom);
        st.z = (unsigned char)max(0, min(99, (int)__fmul_rn(__fsub_rn(1.0f, xn), 99.0f)));
    }
    {
        float xn = __fdiv_rn(__fsub_rn(v.w, mn), denom);
        st.w = (unsigned char)max(0, min(99, (int)__fmul_rn(__fsub_rn(1.0f, xn), 99.0f)));
    }
    ((uchar4*)g_spikes)[gi] = st;
}

// One-hot fill: out[b, t, chw] = (spike[b, chw] == t).
// R2-measured-best shape: each thread owns one uchar4 of spikes and T_PER
// consecutive t values — 1 L2-hit spike load amortized over T_PER coalesced
// streaming float4 stores; 11760 blocks give multi-wave load balancing.
// Block (0,0,0) also resets the reduction/barrier cells for the next replay
// (fill never reads them; it runs strictly after minmax_spike_kernel).
__global__ void __launch_bounds__(256, 8) fill_kernel(float* __restrict__ out) {
    if (blockIdx.x == 0 && blockIdx.y == 0 && blockIdx.z == 0 && threadIdx.x == 0) {
        g_min_bits = 0xFFFFFFFFu;
        g_max_bits = 0u;
        g_bar = 0;
    }
    int chw4 = blockIdx.x * 256 + threadIdx.x;  // 0 .. CHW4-1
    int t0 = blockIdx.y * T_PER;
    int b = blockIdx.z;
    uchar4 st = ((const uchar4*)g_spikes)[b * CHW4 + chw4];
    int sx = st.x, sy = st.y, sz = st.z, sw = st.w;
    float4* base = (float4*)out + (size_t)(b * T_STEPS + t0) * CHW4 + chw4;
    #pragma unroll
    for (int k = 0; k < T_PER; k++) {
        int t = t0 + k;
        float4 o;
        o.x = (sx == t) ? 1.0f : 0.0f;
        o.y = (sy == t) ? 1.0f : 0.0f;
        o.z = (sz == t) ? 1.0f : 0.0f;
        o.w = (sw == t) ? 1.0f : 0.0f;
        __stcs(base + (size_t)k * CHW4, o);
    }
}

extern "C" void kernel_launch(void* const* d_in, const int* in_sizes, int n_in,
                              void* d_out, int out_size) {
    const float* x = (const float*)d_in[0];
    float* out = (float*)d_out;

    minmax_spike_kernel<<<MS_BLOCKS, 256>>>(x);
    dim3 fgrid(CHW4 / 256, T_STEPS / T_PER, BATCH);   // (147, 10, 8)
    fill_kernel<<<fgrid, 256>>>(out);
}

// round 8
// speedup vs baseline: 1.2756x; 1.0541x over previous
#include <cuda_runtime.h>

// Fixed shapes for Latency_78632261255775:
//   x: [8, 3, 224, 224] fp32, T = 100
//   out: [8, 100, 3, 224, 224] fp32
#define N_ELEM   1204224        // 8*3*224*224
#define N4       301056         // N_ELEM/4
#define CHW4     37632          // CHW/4 (float4/uchar4 units per image)
#define BATCH    8
#define T_STEPS  100
#define T_PER    20             // time-steps per fill thread (test mid-point)
#define MM_BLOCKS 1176          // = N4/256

// Reduction cells live at their identities between runs: statically
// initialized, and reset by fill_kernel block (0,0,0) after each run
// (fill never reads them and runs strictly after spike_kernel).
__device__ unsigned int g_min_bits = 0xFFFFFFFFu;  // monotone-uint domain
__device__ unsigned int g_max_bits = 0u;
__device__ unsigned char g_spikes[N_ELEM];

// Order-preserving float <-> uint mapping (monotone for all finite floats).
__device__ __forceinline__ unsigned int f2u(float f) {
    unsigned int u = __float_as_uint(f);
    return (u & 0x80000000u) ? ~u : (u | 0x80000000u);
}
__device__ __forceinline__ float u2f(unsigned int u) {
    u = (u & 0x80000000u) ? (u & 0x7fffffffu) : ~u;
    return __uint_as_float(u);
}

// Kernel 1: min/max with the shortest possible dependency chain.
// One float4 per thread, block reduce, then ONE fire-and-forget RED.MIN/MAX
// per block straight to the global cells — no partials array, no fence, no
// last-block reduction round-trip. Atomics complete before kernel end, so
// kernel 2 sees final values.
__global__ void __launch_bounds__(256, 8) minmax_kernel(const float* __restrict__ x) {
    __shared__ unsigned int s_min[8], s_max[8];
    int tid = threadIdx.x;
    int gi = blockIdx.x * 256 + tid;          // 0 .. N4-1
    float4 v = ((const float4*)x)[gi];
    unsigned int a = f2u(v.x), b_ = f2u(v.y), c = f2u(v.z), d = f2u(v.w);
    unsigned int lmin = min(min(a, b_), min(c, d));
    unsigned int lmax = max(max(a, b_), max(c, d));
    #pragma unroll
    for (int off = 16; off > 0; off >>= 1) {
        lmin = min(lmin, __shfl_down_sync(0xFFFFFFFFu, lmin, off));
        lmax = max(lmax, __shfl_down_sync(0xFFFFFFFFu, lmax, off));
    }
    int wid = tid >> 5, lid = tid & 31;
    if (lid == 0) { s_min[wid] = lmin; s_max[wid] = lmax; }
    __syncthreads();
    if (tid < 32) {
        lmin = (lid < 8) ? s_min[lid] : 0xFFFFFFFFu;
        lmax = (lid < 8) ? s_max[lid] : 0u;
        #pragma unroll
        for (int off = 4; off > 0; off >>= 1) {
            lmin = min(lmin, __shfl_down_sync(0xFFFFFFFFu, lmin, off));
            lmax = max(lmax, __shfl_down_sync(0xFFFFFFFFu, lmax, off));
        }
        if (lid == 0) {
            atomicMin(&g_min_bits, lmin);     // REDG (result unused)
            atomicMax(&g_max_bits, lmax);
        }
    }
}

// Kernel 2: per-element spike index as uint8.
// FP sequence must match the reference exactly (IEEE ops, no fma/reciprocal):
//   xn = (x - min) / ((max - min) + 1e-8)
//   st = clip(trunc((1 - xn) * 99), 0, 99)
__global__ void __launch_bounds__(256, 8) spike_kernel(const float* __restrict__ x) {
    int i = blockIdx.x * 256 + threadIdx.x;   // 0 .. N4-1
    float mn = u2f(g_min_bits);
    float mx = u2f(g_max_bits);
    float denom = __fadd_rn(__fsub_rn(mx, mn), 1e-8f);
    float4 v = ((const float4*)x)[i];         // L2-hit (read by minmax)
    uchar4 st;
    {
        float xn = __fdiv_rn(__fsub_rn(v.x, mn), denom);
        st.x = (unsigned char)max(0, min(99, (int)__fmul_rn(__fsub_rn(1.0f, xn), 99.0f)));
    }
    {
        float xn = __fdiv_rn(__fsub_rn(v.y, mn), denom);
        st.y = (unsigned char)max(0, min(99, (int)__fmul_rn(__fsub_rn(1.0f, xn), 99.0f)));
    }
    {
        float xn = __fdiv_rn(__fsub_rn(v.z, mn), denom);
        st.z = (unsigned char)max(0, min(99, (int)__fmul_rn(__fsub_rn(1.0f, xn), 99.0f)));
    }
    {
        float xn = __fdiv_rn(__fsub_rn(v.w, mn), denom);
        st.w = (unsigned char)max(0, min(99, (int)__fmul_rn(__fsub_rn(1.0f, xn), 99.0f)));
    }
    ((uchar4*)g_spikes)[i] = st;
}

// Kernel 3: one-hot fill, out[b, t, chw] = (spike[b, chw] == t).
// Each thread owns one uchar4 of spikes and T_PER consecutive t values:
// 1 L2-hit spike load amortized over T_PER coalesced streaming float4 stores.
// Block (0,0,0) thread 0 also resets the reduction cells for the next replay.
__global__ void __launch_bounds__(256, 8) fill_kernel(float* __restrict__ out) {
    if (blockIdx.x == 0 && blockIdx.y == 0 && blockIdx.z == 0 && threadIdx.x == 0) {
        g_min_bits = 0xFFFFFFFFu;
        g_max_bits = 0u;
    }
    int chw4 = blockIdx.x * 256 + threadIdx.x;  // 0 .. CHW4-1
    int t0 = blockIdx.y * T_PER;
    int b = blockIdx.z;
    uchar4 st = ((const uchar4*)g_spikes)[b * CHW4 + chw4];
    int sx = st.x, sy = st.y, sz = st.z, sw = st.w;
    float4* base = (float4*)out + (size_t)(b * T_STEPS + t0) * CHW4 + chw4;
    #pragma unroll
    for (int k = 0; k < T_PER; k++) {
        int t = t0 + k;
        float4 o;
        o.x = (sx == t) ? 1.0f : 0.0f;
        o.y = (sy == t) ? 1.0f : 0.0f;
        o.z = (sz == t) ? 1.0f : 0.0f;
        o.w = (sw == t) ? 1.0f : 0.0f;
        __stcs(base + (size_t)k * CHW4, o);
    }
}

extern "C" void kernel_launch(void* const* d_in, const int* in_sizes, int n_in,
                              void* d_out, int out_size) {
    const float* x = (const float*)d_in[0];
    float* out = (float*)d_out;

    minmax_kernel<<<MM_BLOCKS, 256>>>(x);
    spike_kernel<<<MM_BLOCKS, 256>>>(x);
    dim3 fgrid(CHW4 / 256, T_STEPS / T_PER, BATCH);   // (147, 5, 8)
    fill_kernel<<<fgrid, 256>>>(out);
}